// round 4
// baseline (speedup 1.0000x reference)
#include <cuda_runtime.h>
#include <math.h>

#define LSEQ   4096
#define NPAIR  2048      // 16*256/2
#define TPB    256

static __device__ float2 g_Ksp[LSEQ];

// base-16, 3-digit reversal (swap digit0 and digit2)
__device__ __forceinline__ int rev16_3(int i) {
    return ((i & 15) << 8) | (i & 0xF0) | ((i >> 8) & 15);
}

// ---------------- fused K + Ksp kernel (all fp32) ----------------
// g(k) = i*2000*tan(pi*k/L), c(k) = 1 + i*tan(pi*k/L).
// Each 8-lane group handles k and mirror m=L-k (t_m=-t_k), sharing numerators.
__global__ void compute_K_fused(const float* __restrict__ lre, const float* __restrict__ lim,
                                const float* __restrict__ pre, const float* __restrict__ pim,
                                const float* __restrict__ bre, const float* __restrict__ bim,
                                const float* __restrict__ cre, const float* __restrict__ cim)
{
    int gtid = blockIdx.x * blockDim.x + threadIdx.x;
    int k    = gtid >> 3;           // 0..2048
    int sub  = gtid & 7;
    if (k > LSEQ / 2) return;

    const float t = tanf((float)k * 7.6699039394282221e-4f);  // pi/4096
    const float G = 2000.0f * t;

    float a00r=0,a00i=0,a01r=0,a01i=0,a10r=0,a10i=0,a11r=0,a11i=0;
    float b00r=0,b00i=0,b01r=0,b01i=0,b10r=0,b10i=0,b11r=0,b11i=0;

    #pragma unroll
    for (int j = 0; j < 8; j++) {
        int n = sub * 8 + j;
        float lr = lre[n], li = lim[n];
        float pr = pre[n], pi_ = pim[n];
        float br = bre[n], bi = bim[n];
        float cr = cre[n], ci = cim[n];

        float nbr = fmaf(cr, br,  ci * bi),  nbi = fmaf(cr, bi, -ci * br);
        float npr = fmaf(cr, pr,  ci * pi_), npi = fmaf(cr, pi_, -ci * pr);
        float pbr = fmaf(pr, br,  pi_ * bi), pbi = fmaf(pr, bi, -pi_ * br);
        float pp  = fmaf(pr, pr,  pi_ * pi_);

        {
            float ex = -lr, ey = G - li;
            float r  = 1.0f / fmaf(ex, ex, ey * ey);
            float dr = ex * r, di = -ey * r;
            a00r = fmaf(dr, nbr, fmaf(-di, nbi, a00r));
            a00i = fmaf(dr, nbi, fmaf( di, nbr, a00i));
            a01r = fmaf(dr, npr, fmaf(-di, npi, a01r));
            a01i = fmaf(dr, npi, fmaf( di, npr, a01i));
            a10r = fmaf(dr, pbr, fmaf(-di, pbi, a10r));
            a10i = fmaf(dr, pbi, fmaf( di, pbr, a10i));
            a11r = fmaf(dr, pp, a11r);
            a11i = fmaf(di, pp, a11i);
        }
        {
            float ex = -lr, ey = -G - li;
            float r  = 1.0f / fmaf(ex, ex, ey * ey);
            float dr = ex * r, di = -ey * r;
            b00r = fmaf(dr, nbr, fmaf(-di, nbi, b00r));
            b00i = fmaf(dr, nbi, fmaf( di, nbr, b00i));
            b01r = fmaf(dr, npr, fmaf(-di, npi, b01r));
            b01i = fmaf(dr, npi, fmaf( di, npr, b01i));
            b10r = fmaf(dr, pbr, fmaf(-di, pbi, b10r));
            b10i = fmaf(dr, pbi, fmaf( di, pbr, b10i));
            b11r = fmaf(dr, pp, b11r);
            b11i = fmaf(di, pp, b11i);
        }
    }

    #pragma unroll
    for (int m = 1; m < 8; m <<= 1) {
        a00r += __shfl_xor_sync(0xffffffffu, a00r, m);
        a00i += __shfl_xor_sync(0xffffffffu, a00i, m);
        a01r += __shfl_xor_sync(0xffffffffu, a01r, m);
        a01i += __shfl_xor_sync(0xffffffffu, a01i, m);
        a10r += __shfl_xor_sync(0xffffffffu, a10r, m);
        a10i += __shfl_xor_sync(0xffffffffu, a10i, m);
        a11r += __shfl_xor_sync(0xffffffffu, a11r, m);
        a11i += __shfl_xor_sync(0xffffffffu, a11i, m);
        b00r += __shfl_xor_sync(0xffffffffu, b00r, m);
        b00i += __shfl_xor_sync(0xffffffffu, b00i, m);
        b01r += __shfl_xor_sync(0xffffffffu, b01r, m);
        b01i += __shfl_xor_sync(0xffffffffu, b01i, m);
        b10r += __shfl_xor_sync(0xffffffffu, b10r, m);
        b10i += __shfl_xor_sync(0xffffffffu, b10i, m);
        b11r += __shfl_xor_sync(0xffffffffu, b11r, m);
        b11i += __shfl_xor_sync(0xffffffffu, b11i, m);
    }

    if (sub == 0) {
        float Kk_r, Kk_i, Km_r, Km_i;
        {
            float numr = a01r * a10r - a01i * a10i;
            float numi = a01r * a10i + a01i * a10r;
            float der  = 1.0f + a11r, dei = a11i;
            float dd   = 1.0f / fmaf(der, der, dei * dei);
            float ar = a00r - (numr * der + numi * dei) * dd;
            float ai = a00i - (numi * der - numr * dei) * dd;
            Kk_r = fmaf(-t, ai, ar); Kk_i = fmaf(t, ar, ai);
        }
        {
            float numr = b01r * b10r - b01i * b10i;
            float numi = b01r * b10i + b01i * b10r;
            float der  = 1.0f + b11r, dei = b11i;
            float dd   = 1.0f / fmaf(der, der, dei * dei);
            float ar = b00r - (numr * der + numi * dei) * dd;
            float ai = b00i - (numi * der - numr * dei) * dd;
            Km_r = fmaf(t, ai, ar); Km_i = fmaf(-t, ar, ai);
        }
        const float sc = 0.5f / (float)LSEQ;
        float sr = (Kk_r + Km_r) * sc;
        float si = (Kk_i - Km_i) * sc;
        int mk = (LSEQ - k) & (LSEQ - 1);
        g_Ksp[rev16_3(k)]  = make_float2(sr,  si);
        g_Ksp[rev16_3(mk)] = make_float2(sr, -si);
    }
}

// ---------------- fp32 FFT machinery ----------------
#define SIDX16(i) ((i) + ((i) >> 4))   // pad 1 per 16 complex -> conflict-free

__device__ __forceinline__ float2 f2add(float2 a, float2 b){ return make_float2(a.x+b.x, a.y+b.y); }
__device__ __forceinline__ float2 f2sub(float2 a, float2 b){ return make_float2(a.x-b.x, a.y-b.y); }
__device__ __forceinline__ float2 cmulf(float2 a, float2 b){
    return make_float2(fmaf(a.x, b.x, -a.y*b.y), fmaf(a.x, b.y, a.y*b.x));
}
__device__ __forceinline__ float2 cmulk(float2 z, float cr, float ci){
    return make_float2(fmaf(z.x, cr, -z.y*ci), fmaf(z.x, ci, z.y*cr));
}
template<int SGN>
__device__ __forceinline__ float2 mul_is(float2 z){  // z * (i*SGN)
    return (SGN > 0) ? make_float2(-z.y, z.x) : make_float2(z.y, -z.x);
}

template<int SGN>
__device__ __forceinline__ void dft8(float2* v)
{
    const float C = 0.70710678118654752440f;
    const float S = (float)SGN;
    float2 u0 = f2add(v[0], v[4]), w0 = f2sub(v[0], v[4]);
    float2 u1 = f2add(v[1], v[5]), w1 = f2sub(v[1], v[5]);
    float2 u2 = f2add(v[2], v[6]), w2 = f2sub(v[2], v[6]);
    float2 u3 = f2add(v[3], v[7]), w3 = f2sub(v[3], v[7]);
    w1 = make_float2(C * (w1.x - S * w1.y),  C * (S * w1.x + w1.y));
    w2 = mul_is<SGN>(w2);
    w3 = make_float2(-C * (w3.x + S * w3.y), C * (S * w3.x - w3.y));
    float2 p0 = f2add(u0, u2), q0 = f2sub(u0, u2);
    float2 p1 = f2add(u1, u3), q1 = mul_is<SGN>(f2sub(u1, u3));
    v[0] = f2add(p0, p1); v[4] = f2sub(p0, p1);
    v[2] = f2add(q0, q1); v[6] = f2sub(q0, q1);
    float2 r0 = f2add(w0, w2), s0 = f2sub(w0, w2);
    float2 r1 = f2add(w1, w3), s1 = mul_is<SGN>(f2sub(w1, w3));
    v[1] = f2add(r0, r1); v[5] = f2sub(r0, r1);
    v[3] = f2add(s0, s1); v[7] = f2sub(s0, s1);
}

// 16-point DFT, natural order in/out: two dft8 (even/odd) + combine.
template<int SGN>
__device__ __forceinline__ void dft16(float2* v)
{
    const float C  = 0.70710678118654752440f;
    const float c8 = 0.92387953251128675613f;   // cos(pi/8)
    const float s8 = 0.38268343236508977173f;   // sin(pi/8)
    const float S  = (float)SGN;
    float2 e[8], o[8];
    #pragma unroll
    for (int j = 0; j < 8; j++) { e[j] = v[2*j]; o[j] = v[2*j+1]; }
    dft8<SGN>(e);
    dft8<SGN>(o);
    o[1] = cmulk(o[1],  c8, S * s8);
    o[2] = cmulk(o[2],  C,  S * C );
    o[3] = cmulk(o[3],  s8, S * c8);
    o[4] = mul_is<SGN>(o[4]);
    o[5] = cmulk(o[5], -s8, S * c8);
    o[6] = cmulk(o[6], -C,  S * C );
    o[7] = cmulk(o[7], -c8, S * s8);
    #pragma unroll
    for (int k = 0; k < 8; k++) {
        v[k]     = f2add(e[k], o[k]);
        v[k + 8] = f2sub(e[k], o[k]);
    }
}

// apply w_M^(SGN*a*j) to v[j], j=1..15. Two sincos (w1, w8), short product trees.
template<int SGN, int M>
__device__ __forceinline__ void twiddle16(float2* v, int a)
{
    const float kAng = (float)SGN * 6.283185307179586f / (float)M;
    float sn, cs;
    __sincosf(kAng * (float)a, &sn, &cs);
    float2 w1 = make_float2(cs, sn);
    __sincosf(kAng * (float)(8 * a), &sn, &cs);
    float2 w8 = make_float2(cs, sn);
    float2 w2 = cmulf(w1, w1);
    float2 w3 = cmulf(w2, w1);
    float2 w4 = cmulf(w2, w2);
    v[1]  = cmulf(v[1], w1);
    v[2]  = cmulf(v[2], w2);
    v[3]  = cmulf(v[3], w3);
    v[4]  = cmulf(v[4], w4);
    v[5]  = cmulf(v[5], cmulf(w4, w1));
    v[6]  = cmulf(v[6], cmulf(w4, w2));
    v[7]  = cmulf(v[7], cmulf(w4, w3));
    v[8]  = cmulf(v[8], w8);
    v[9]  = cmulf(v[9],  cmulf(w8, w1));
    v[10] = cmulf(v[10], cmulf(w8, w2));
    v[11] = cmulf(v[11], cmulf(w8, w3));
    float2 w12 = cmulf(w8, w4);
    v[12] = cmulf(v[12], w12);
    v[13] = cmulf(v[13], cmulf(w12, w1));
    v[14] = cmulf(v[14], cmulf(w12, w2));
    v[15] = cmulf(v[15], cmulf(w12, w3));
}

// middle radix-16 pass in shared memory (H=16, M=256)
template<int SGN>
__device__ __forceinline__ void stage16_sh(float2* s, int t)
{
    int base = (t >> 4) * 256 + (t & 15);
    int a    = t & 15;
    float2 v[16];
    #pragma unroll
    for (int i = 0; i < 16; i++)
        v[i] = s[SIDX16(base + 16 * i)];
    if (SGN < 0) { dft16<SGN>(v); twiddle16<SGN, 256>(v, a); }
    else         { twiddle16<SGN, 256>(v, a); dft16<SGN>(v); }
    #pragma unroll
    for (int i = 0; i < 16; i++)
        s[SIDX16(base + 16 * i)] = v[i];
}

// ---------------- main kernel: 2 real channels per block ----------------
__global__ __launch_bounds__(TPB, 2)
void s4_fftconv_kernel(const float* __restrict__ x, float* __restrict__ y)
{
    __shared__ float2 s[LSEQ + (LSEQ >> 4)];
    const int t = threadIdx.x;
    const size_t base = (size_t)blockIdx.x * 2u * LSEQ;
    const float* x1 = x + base;
    const float* x2 = x + base + LSEQ;
    float* y1 = y + base;
    float* y2 = y + base + LSEQ;

    float2 v[16];

    // ---- forward stage 0 (M=4096, H=256): global -> regs -> shared
    #pragma unroll
    for (int b = 0; b < 16; b++)
        v[b] = make_float2(x1[t + 256 * b], x2[t + 256 * b]);
    dft16<-1>(v);
    twiddle16<-1, 4096>(v, t);
    #pragma unroll
    for (int j = 0; j < 16; j++)
        s[SIDX16(t + 256 * j)] = v[j];
    __syncthreads();

    stage16_sh<-1>(s, t);     // forward stage 1 (M=256)
    __syncthreads();

    // ---- fused: fwd stage 2 (H=1, M=16, a=0) + Ksp + inv stage 2 — in regs
    {
        const int p0 = 17 * t;            // SIDX16(16*t)
        #pragma unroll
        for (int j = 0; j < 16; j++)
            v[j] = s[p0 + j];
        dft16<-1>(v);
        #pragma unroll
        for (int j = 0; j < 16; j++)
            v[j] = cmulf(v[j], __ldg(&g_Ksp[16 * t + j]));
        dft16<1>(v);
        #pragma unroll
        for (int j = 0; j < 16; j++)
            s[p0 + j] = v[j];
    }
    __syncthreads();

    stage16_sh<1>(s, t);      // inverse stage 1
    __syncthreads();

    // ---- inverse stage 0 (M=4096, H=256): shared -> regs -> global
    #pragma unroll
    for (int j = 0; j < 16; j++)
        v[j] = s[SIDX16(t + 256 * j)];
    twiddle16<1, 4096>(v, t);
    dft16<1>(v);
    #pragma unroll
    for (int b = 0; b < 16; b++) {
        y1[t + 256 * b] = v[b].x;
        y2[t + 256 * b] = v[b].y;
    }
}

extern "C" void kernel_launch(void* const* d_in, const int* in_sizes, int n_in,
                              void* d_out, int out_size)
{
    const float* x   = (const float*)d_in[0];
    const float* lre = (const float*)d_in[1];
    const float* lim = (const float*)d_in[2];
    const float* pre = (const float*)d_in[3];
    const float* pim = (const float*)d_in[4];
    const float* bre = (const float*)d_in[5];
    const float* bim = (const float*)d_in[6];
    const float* cre = (const float*)d_in[7];
    const float* cim = (const float*)d_in[8];
    float* y = (float*)d_out;

    compute_K_fused<<<(((LSEQ / 2 + 1) * 8) + 255) / 256, 256>>>(lre, lim, pre, pim, bre, bim, cre, cim);
    s4_fftconv_kernel<<<NPAIR, TPB>>>(x, y);
}

// round 5
// speedup vs baseline: 1.0465x; 1.0465x over previous
#include <cuda_runtime.h>
#include <math.h>

#define LSEQ   4096
#define NPAIR  2048      // 16*256/2
#define TPB    512

static __device__ float2 g_Ksp[LSEQ];

// base-8, 4-digit reversal
__device__ __forceinline__ int digitrev84(int i) {
    return ((i & 7) << 9) | (((i >> 3) & 7) << 6) |
           (((i >> 6) & 7) << 3) | ((i >> 9) & 7);
}

// ---------------- fused K + Ksp kernel (all fp32) ----------------
// g(k) = i*2000*tan(pi*k/L), c(k) = 1 + i*tan(pi*k/L).
// 16 lanes per k (4 states each); each group handles k and mirror L-k.
__global__ void compute_K_fused(const float* __restrict__ lre, const float* __restrict__ lim,
                                const float* __restrict__ pre, const float* __restrict__ pim,
                                const float* __restrict__ bre, const float* __restrict__ bim,
                                const float* __restrict__ cre, const float* __restrict__ cim)
{
    int gtid = blockIdx.x * blockDim.x + threadIdx.x;
    int k    = gtid >> 4;           // 0..2048
    int sub  = gtid & 15;
    if (k > LSEQ / 2) return;

    const float t = tanf((float)k * 7.6699039394282221e-4f);  // pi/4096
    const float G = 2000.0f * t;

    float a00r=0,a00i=0,a01r=0,a01i=0,a10r=0,a10i=0,a11r=0,a11i=0;
    float b00r=0,b00i=0,b01r=0,b01i=0,b10r=0,b10i=0,b11r=0,b11i=0;

    #pragma unroll
    for (int j = 0; j < 4; j++) {
        int n = sub * 4 + j;
        float lr = lre[n], li = lim[n];
        float pr = pre[n], pi_ = pim[n];
        float br = bre[n], bi = bim[n];
        float cr = cre[n], ci = cim[n];

        float nbr = fmaf(cr, br,  ci * bi),  nbi = fmaf(cr, bi, -ci * br);
        float npr = fmaf(cr, pr,  ci * pi_), npi = fmaf(cr, pi_, -ci * pr);
        float pbr = fmaf(pr, br,  pi_ * bi), pbi = fmaf(pr, bi, -pi_ * br);
        float pp  = fmaf(pr, pr,  pi_ * pi_);

        {
            float ex = -lr, ey = G - li;
            float r  = 1.0f / fmaf(ex, ex, ey * ey);
            float dr = ex * r, di = -ey * r;
            a00r = fmaf(dr, nbr, fmaf(-di, nbi, a00r));
            a00i = fmaf(dr, nbi, fmaf( di, nbr, a00i));
            a01r = fmaf(dr, npr, fmaf(-di, npi, a01r));
            a01i = fmaf(dr, npi, fmaf( di, npr, a01i));
            a10r = fmaf(dr, pbr, fmaf(-di, pbi, a10r));
            a10i = fmaf(dr, pbi, fmaf( di, pbr, a10i));
            a11r = fmaf(dr, pp, a11r);
            a11i = fmaf(di, pp, a11i);
        }
        {
            float ex = -lr, ey = -G - li;
            float r  = 1.0f / fmaf(ex, ex, ey * ey);
            float dr = ex * r, di = -ey * r;
            b00r = fmaf(dr, nbr, fmaf(-di, nbi, b00r));
            b00i = fmaf(dr, nbi, fmaf( di, nbr, b00i));
            b01r = fmaf(dr, npr, fmaf(-di, npi, b01r));
            b01i = fmaf(dr, npi, fmaf( di, npr, b01i));
            b10r = fmaf(dr, pbr, fmaf(-di, pbi, b10r));
            b10i = fmaf(dr, pbi, fmaf( di, pbr, b10i));
            b11r = fmaf(dr, pp, b11r);
            b11i = fmaf(di, pp, b11i);
        }
    }

    #pragma unroll
    for (int m = 1; m < 16; m <<= 1) {
        a00r += __shfl_xor_sync(0xffffffffu, a00r, m);
        a00i += __shfl_xor_sync(0xffffffffu, a00i, m);
        a01r += __shfl_xor_sync(0xffffffffu, a01r, m);
        a01i += __shfl_xor_sync(0xffffffffu, a01i, m);
        a10r += __shfl_xor_sync(0xffffffffu, a10r, m);
        a10i += __shfl_xor_sync(0xffffffffu, a10i, m);
        a11r += __shfl_xor_sync(0xffffffffu, a11r, m);
        a11i += __shfl_xor_sync(0xffffffffu, a11i, m);
        b00r += __shfl_xor_sync(0xffffffffu, b00r, m);
        b00i += __shfl_xor_sync(0xffffffffu, b00i, m);
        b01r += __shfl_xor_sync(0xffffffffu, b01r, m);
        b01i += __shfl_xor_sync(0xffffffffu, b01i, m);
        b10r += __shfl_xor_sync(0xffffffffu, b10r, m);
        b10i += __shfl_xor_sync(0xffffffffu, b10i, m);
        b11r += __shfl_xor_sync(0xffffffffu, b11r, m);
        b11i += __shfl_xor_sync(0xffffffffu, b11i, m);
    }

    if (sub == 0) {
        float Kk_r, Kk_i, Km_r, Km_i;
        {
            float numr = a01r * a10r - a01i * a10i;
            float numi = a01r * a10i + a01i * a10r;
            float der  = 1.0f + a11r, dei = a11i;
            float dd   = 1.0f / fmaf(der, der, dei * dei);
            float ar = a00r - (numr * der + numi * dei) * dd;
            float ai = a00i - (numi * der - numr * dei) * dd;
            Kk_r = fmaf(-t, ai, ar); Kk_i = fmaf(t, ar, ai);
        }
        {
            float numr = b01r * b10r - b01i * b10i;
            float numi = b01r * b10i + b01i * b10r;
            float der  = 1.0f + b11r, dei = b11i;
            float dd   = 1.0f / fmaf(der, der, dei * dei);
            float ar = b00r - (numr * der + numi * dei) * dd;
            float ai = b00i - (numi * der - numr * dei) * dd;
            Km_r = fmaf(t, ai, ar); Km_i = fmaf(-t, ar, ai);
        }
        const float sc = 0.5f / (float)LSEQ;
        float sr = (Kk_r + Km_r) * sc;
        float si = (Kk_i - Km_i) * sc;
        int mk = (LSEQ - k) & (LSEQ - 1);
        g_Ksp[digitrev84(k)]  = make_float2(sr,  si);
        g_Ksp[digitrev84(mk)] = make_float2(sr, -si);
    }
}

// ---------------- fp32 FFT machinery ----------------
#define SIDX(i) ((i) + ((i) >> 3))   // pad 1 per 8 complex

__device__ __forceinline__ float2 f2add(float2 a, float2 b){ return make_float2(a.x+b.x, a.y+b.y); }
__device__ __forceinline__ float2 f2sub(float2 a, float2 b){ return make_float2(a.x-b.x, a.y-b.y); }
__device__ __forceinline__ float2 cmulf(float2 a, float2 b){
    return make_float2(fmaf(a.x, b.x, -a.y*b.y), fmaf(a.x, b.y, a.y*b.x));
}
template<int SGN>
__device__ __forceinline__ float2 mul_is(float2 z){  // z * (i*SGN)
    return (SGN > 0) ? make_float2(-z.y, z.x) : make_float2(z.y, -z.x);
}

template<int SGN>
__device__ __forceinline__ void dft8(float2* v)
{
    const float C = 0.70710678118654752440f;
    const float S = (float)SGN;
    float2 u0 = f2add(v[0], v[4]), w0 = f2sub(v[0], v[4]);
    float2 u1 = f2add(v[1], v[5]), w1 = f2sub(v[1], v[5]);
    float2 u2 = f2add(v[2], v[6]), w2 = f2sub(v[2], v[6]);
    float2 u3 = f2add(v[3], v[7]), w3 = f2sub(v[3], v[7]);
    w1 = make_float2(C * (w1.x - S * w1.y),  C * (S * w1.x + w1.y));
    w2 = mul_is<SGN>(w2);
    w3 = make_float2(-C * (w3.x + S * w3.y), C * (S * w3.x - w3.y));
    float2 p0 = f2add(u0, u2), q0 = f2sub(u0, u2);
    float2 p1 = f2add(u1, u3), q1 = mul_is<SGN>(f2sub(u1, u3));
    v[0] = f2add(p0, p1); v[4] = f2sub(p0, p1);
    v[2] = f2add(q0, q1); v[6] = f2sub(q0, q1);
    float2 r0 = f2add(w0, w2), s0 = f2sub(w0, w2);
    float2 r1 = f2add(w1, w3), s1 = mul_is<SGN>(f2sub(w1, w3));
    v[1] = f2add(r0, r1); v[5] = f2sub(r0, r1);
    v[3] = f2add(s0, s1); v[7] = f2sub(s0, s1);
}

// apply w_M^(SGN*a*j) to v[j], j=1..7 — powers via depth-3 tree
template<int SGN, int M>
__device__ __forceinline__ void twiddles(float2* v, int a)
{
    const float kAng = (float)SGN * 6.283185307179586f / (float)M;
    float sn, cs;
    __sincosf(kAng * (float)a, &sn, &cs);
    float2 w1 = make_float2(cs, sn);
    float2 w2 = cmulf(w1, w1);
    float2 w3 = cmulf(w2, w1);
    float2 w4 = cmulf(w2, w2);
    float2 w5 = cmulf(w3, w2);
    float2 w6 = cmulf(w3, w3);
    float2 w7 = cmulf(w4, w3);
    v[1] = cmulf(v[1], w1); v[2] = cmulf(v[2], w2);
    v[3] = cmulf(v[3], w3); v[4] = cmulf(v[4], w4);
    v[5] = cmulf(v[5], w5); v[6] = cmulf(v[6], w6);
    v[7] = cmulf(v[7], w7);
}

// 8x8 transpose across 8 lanes (lane index a = t&7), 8 float2 regs.
// Step k exchanges (a,j)<->(a^k,j^k) whenever bit k of lane != bit k of reg.
// All register indices are compile-time; lane-dependence handled by SEL.
__device__ __forceinline__ void transpose8(float2* v, int a)
{
    #pragma unroll
    for (int k = 1; k < 8; k <<= 1) {
        bool up = (a & k) != 0;
        #pragma unroll
        for (int j0 = 0; j0 < 8; j0++) {
            if ((j0 & k) == 0) {
                int j1 = j0 | k;
                float sx = up ? v[j0].x : v[j1].x;
                float sy = up ? v[j0].y : v[j1].y;
                sx = __shfl_xor_sync(0xffffffffu, sx, k);
                sy = __shfl_xor_sync(0xffffffffu, sy, k);
                if (up) { v[j0].x = sx; v[j0].y = sy; }
                else    { v[j1].x = sx; v[j1].y = sy; }
            }
        }
    }
}

// one radix-8 pass in shared memory (H=64, M=512)
template<int SGN>
__device__ __forceinline__ void stage64_sh(float2* s, int t)
{
    int base = (t >> 6) * 512 + (t & 63);
    int a    = t & 63;
    float2 v[8];
    #pragma unroll
    for (int i = 0; i < 8; i++)
        v[i] = s[SIDX(base + 64 * i)];
    if (SGN < 0) { dft8<SGN>(v); twiddles<SGN, 512>(v, a); }
    else         { twiddles<SGN, 512>(v, a); dft8<SGN>(v); }
    #pragma unroll
    for (int i = 0; i < 8; i++)
        s[SIDX(base + 64 * i)] = v[i];
}

// ---------------- main kernel: 2 real channels per block ----------------
__global__ __launch_bounds__(TPB, 2)
void s4_fftconv_kernel(const float* __restrict__ x, float* __restrict__ y)
{
    __shared__ float2 s[LSEQ + (LSEQ >> 3)];
    const int t = threadIdx.x;
    const size_t base = (size_t)blockIdx.x * 2u * LSEQ;
    const float* x1 = x + base;
    const float* x2 = x + base + LSEQ;
    float* y1 = y + base;
    float* y2 = y + base + LSEQ;

    float2 v[8];

    // ---- forward stage 0 (M=4096, H=512): global -> regs -> shared
    #pragma unroll
    for (int b = 0; b < 8; b++)
        v[b] = make_float2(x1[t + 512 * b], x2[t + 512 * b]);
    dft8<-1>(v);
    twiddles<-1, 4096>(v, t);
    #pragma unroll
    for (int j = 0; j < 8; j++)
        s[SIDX(t + 512 * j)] = v[j];
    __syncthreads();

    stage64_sh<-1>(s, t);     // forward stage 1 (M=512, H=64)
    __syncthreads();

    // ---- merged middle: fwd H=8, transpose, fwd H=1, Ksp, inv H=1,
    //      transpose back, inv H=8 — one smem round trip, no extra barriers
    {
        const int g = t >> 3;
        const int a = t & 7;
        const int mbase = 64 * g + a;
        #pragma unroll
        for (int i = 0; i < 8; i++)
            v[i] = s[SIDX(mbase + 8 * i)];
        dft8<-1>(v);
        twiddles<-1, 64>(v, a);
        transpose8(v, a);                 // now v[d] = position 64g + 8a + d
        dft8<-1>(v);                      // H=1 stage (no twiddle)
        #pragma unroll
        for (int d = 0; d < 8; d++)
            v[d] = cmulf(v[d], __ldg(&g_Ksp[8 * t + d]));
        dft8<1>(v);                       // inverse H=1
        transpose8(v, a);
        twiddles<1, 64>(v, a);
        dft8<1>(v);                       // inverse H=8
        #pragma unroll
        for (int i = 0; i < 8; i++)
            s[SIDX(mbase + 8 * i)] = v[i];
    }
    __syncthreads();

    stage64_sh<1>(s, t);      // inverse stage 1
    __syncthreads();

    // ---- inverse stage 0 (M=4096, H=512): shared -> regs -> global
    #pragma unroll
    for (int j = 0; j < 8; j++)
        v[j] = s[SIDX(t + 512 * j)];
    twiddles<1, 4096>(v, t);
    dft8<1>(v);
    #pragma unroll
    for (int b = 0; b < 8; b++) {
        y1[t + 512 * b] = v[b].x;
        y2[t + 512 * b] = v[b].y;
    }
}

extern "C" void kernel_launch(void* const* d_in, const int* in_sizes, int n_in,
                              void* d_out, int out_size)
{
    const float* x   = (const float*)d_in[0];
    const float* lre = (const float*)d_in[1];
    const float* lim = (const float*)d_in[2];
    const float* pre = (const float*)d_in[3];
    const float* pim = (const float*)d_in[4];
    const float* bre = (const float*)d_in[5];
    const float* bim = (const float*)d_in[6];
    const float* cre = (const float*)d_in[7];
    const float* cim = (const float*)d_in[8];
    float* y = (float*)d_out;

    compute_K_fused<<<(((LSEQ / 2 + 1) * 16) + 255) / 256, 256>>>(lre, lim, pre, pim, bre, bim, cre, cim);
    s4_fftconv_kernel<<<NPAIR, TPB>>>(x, y);
}

// round 6
// speedup vs baseline: 1.1929x; 1.1399x over previous
#include <cuda_runtime.h>
#include <math.h>

#define LSEQ   4096
#define NPAIR  2048      // 16*256/2
#define TPB    512

static __device__ float2 g_Ksp[LSEQ];

// base-8, 4-digit reversal
__device__ __forceinline__ int digitrev84(int i) {
    return ((i & 7) << 9) | (((i >> 3) & 7) << 6) |
           (((i >> 6) & 7) << 3) | ((i >> 9) & 7);
}

// ---------------- fused K + Ksp kernel (all fp32) ----------------
// g(k) = i*2000*tan(pi*k/L), c(k) = 1 + i*tan(pi*k/L).
// 16 lanes per k (4 states each); each group handles k and mirror L-k.
__global__ void compute_K_fused(const float* __restrict__ lre, const float* __restrict__ lim,
                                const float* __restrict__ pre, const float* __restrict__ pim,
                                const float* __restrict__ bre, const float* __restrict__ bim,
                                const float* __restrict__ cre, const float* __restrict__ cim)
{
    int gtid = blockIdx.x * blockDim.x + threadIdx.x;
    int k    = gtid >> 4;           // 0..2048
    int sub  = gtid & 15;
    if (k > LSEQ / 2) return;

    const float t = tanf((float)k * 7.6699039394282221e-4f);  // pi/4096
    const float G = 2000.0f * t;

    float a00r=0,a00i=0,a01r=0,a01i=0,a10r=0,a10i=0,a11r=0,a11i=0;
    float b00r=0,b00i=0,b01r=0,b01i=0,b10r=0,b10i=0,b11r=0,b11i=0;

    #pragma unroll
    for (int j = 0; j < 4; j++) {
        int n = sub * 4 + j;
        float lr = lre[n], li = lim[n];
        float pr = pre[n], pi_ = pim[n];
        float br = bre[n], bi = bim[n];
        float cr = cre[n], ci = cim[n];

        float nbr = fmaf(cr, br,  ci * bi),  nbi = fmaf(cr, bi, -ci * br);
        float npr = fmaf(cr, pr,  ci * pi_), npi = fmaf(cr, pi_, -ci * pr);
        float pbr = fmaf(pr, br,  pi_ * bi), pbi = fmaf(pr, bi, -pi_ * br);
        float pp  = fmaf(pr, pr,  pi_ * pi_);

        {
            float ex = -lr, ey = G - li;
            float r  = 1.0f / fmaf(ex, ex, ey * ey);
            float dr = ex * r, di = -ey * r;
            a00r = fmaf(dr, nbr, fmaf(-di, nbi, a00r));
            a00i = fmaf(dr, nbi, fmaf( di, nbr, a00i));
            a01r = fmaf(dr, npr, fmaf(-di, npi, a01r));
            a01i = fmaf(dr, npi, fmaf( di, npr, a01i));
            a10r = fmaf(dr, pbr, fmaf(-di, pbi, a10r));
            a10i = fmaf(dr, pbi, fmaf( di, pbr, a10i));
            a11r = fmaf(dr, pp, a11r);
            a11i = fmaf(di, pp, a11i);
        }
        {
            float ex = -lr, ey = -G - li;
            float r  = 1.0f / fmaf(ex, ex, ey * ey);
            float dr = ex * r, di = -ey * r;
            b00r = fmaf(dr, nbr, fmaf(-di, nbi, b00r));
            b00i = fmaf(dr, nbi, fmaf( di, nbr, b00i));
            b01r = fmaf(dr, npr, fmaf(-di, npi, b01r));
            b01i = fmaf(dr, npi, fmaf( di, npr, b01i));
            b10r = fmaf(dr, pbr, fmaf(-di, pbi, b10r));
            b10i = fmaf(dr, pbi, fmaf( di, pbr, b10i));
            b11r = fmaf(dr, pp, b11r);
            b11i = fmaf(di, pp, b11i);
        }
    }

    #pragma unroll
    for (int m = 1; m < 16; m <<= 1) {
        a00r += __shfl_xor_sync(0xffffffffu, a00r, m);
        a00i += __shfl_xor_sync(0xffffffffu, a00i, m);
        a01r += __shfl_xor_sync(0xffffffffu, a01r, m);
        a01i += __shfl_xor_sync(0xffffffffu, a01i, m);
        a10r += __shfl_xor_sync(0xffffffffu, a10r, m);
        a10i += __shfl_xor_sync(0xffffffffu, a10i, m);
        a11r += __shfl_xor_sync(0xffffffffu, a11r, m);
        a11i += __shfl_xor_sync(0xffffffffu, a11i, m);
        b00r += __shfl_xor_sync(0xffffffffu, b00r, m);
        b00i += __shfl_xor_sync(0xffffffffu, b00i, m);
        b01r += __shfl_xor_sync(0xffffffffu, b01r, m);
        b01i += __shfl_xor_sync(0xffffffffu, b01i, m);
        b10r += __shfl_xor_sync(0xffffffffu, b10r, m);
        b10i += __shfl_xor_sync(0xffffffffu, b10i, m);
        b11r += __shfl_xor_sync(0xffffffffu, b11r, m);
        b11i += __shfl_xor_sync(0xffffffffu, b11i, m);
    }

    if (sub == 0) {
        float Kk_r, Kk_i, Km_r, Km_i;
        {
            float numr = a01r * a10r - a01i * a10i;
            float numi = a01r * a10i + a01i * a10r;
            float der  = 1.0f + a11r, dei = a11i;
            float dd   = 1.0f / fmaf(der, der, dei * dei);
            float ar = a00r - (numr * der + numi * dei) * dd;
            float ai = a00i - (numi * der - numr * dei) * dd;
            Kk_r = fmaf(-t, ai, ar); Kk_i = fmaf(t, ar, ai);
        }
        {
            float numr = b01r * b10r - b01i * b10i;
            float numi = b01r * b10i + b01i * b10r;
            float der  = 1.0f + b11r, dei = b11i;
            float dd   = 1.0f / fmaf(der, der, dei * dei);
            float ar = b00r - (numr * der + numi * dei) * dd;
            float ai = b00i - (numi * der - numr * dei) * dd;
            Km_r = fmaf(t, ai, ar); Km_i = fmaf(-t, ar, ai);
        }
        const float sc = 0.5f / (float)LSEQ;
        float sr = (Kk_r + Km_r) * sc;
        float si = (Kk_i - Km_i) * sc;
        int mk = (LSEQ - k) & (LSEQ - 1);
        g_Ksp[digitrev84(k)]  = make_float2(sr,  si);
        g_Ksp[digitrev84(mk)] = make_float2(sr, -si);
    }
}

// ---------------- fp32 FFT machinery ----------------
#define SIDX(i) ((i) + ((i) >> 3))   // pad 1 per 8 complex

__device__ __forceinline__ float2 f2add(float2 a, float2 b){ return make_float2(a.x+b.x, a.y+b.y); }
__device__ __forceinline__ float2 f2sub(float2 a, float2 b){ return make_float2(a.x-b.x, a.y-b.y); }
__device__ __forceinline__ float2 cmulf(float2 a, float2 b){
    return make_float2(fmaf(a.x, b.x, -a.y*b.y), fmaf(a.x, b.y, a.y*b.x));
}
template<int SGN>
__device__ __forceinline__ float2 mul_is(float2 z){  // z * (i*SGN)
    return (SGN > 0) ? make_float2(-z.y, z.x) : make_float2(z.y, -z.x);
}

template<int SGN>
__device__ __forceinline__ void dft8(float2* v)
{
    const float C = 0.70710678118654752440f;
    const float S = (float)SGN;
    float2 u0 = f2add(v[0], v[4]), w0 = f2sub(v[0], v[4]);
    float2 u1 = f2add(v[1], v[5]), w1 = f2sub(v[1], v[5]);
    float2 u2 = f2add(v[2], v[6]), w2 = f2sub(v[2], v[6]);
    float2 u3 = f2add(v[3], v[7]), w3 = f2sub(v[3], v[7]);
    w1 = make_float2(C * (w1.x - S * w1.y),  C * (S * w1.x + w1.y));
    w2 = mul_is<SGN>(w2);
    w3 = make_float2(-C * (w3.x + S * w3.y), C * (S * w3.x - w3.y));
    float2 p0 = f2add(u0, u2), q0 = f2sub(u0, u2);
    float2 p1 = f2add(u1, u3), q1 = mul_is<SGN>(f2sub(u1, u3));
    v[0] = f2add(p0, p1); v[4] = f2sub(p0, p1);
    v[2] = f2add(q0, q1); v[6] = f2sub(q0, q1);
    float2 r0 = f2add(w0, w2), s0 = f2sub(w0, w2);
    float2 r1 = f2add(w1, w3), s1 = mul_is<SGN>(f2sub(w1, w3));
    v[1] = f2add(r0, r1); v[5] = f2sub(r0, r1);
    v[3] = f2add(s0, s1); v[7] = f2sub(s0, s1);
}

// apply w_M^(SGN*a*j) to v[j], j=1..7 — powers via depth-3 tree
template<int SGN, int M>
__device__ __forceinline__ void twiddles(float2* v, int a)
{
    const float kAng = (float)SGN * 6.283185307179586f / (float)M;
    float sn, cs;
    __sincosf(kAng * (float)a, &sn, &cs);
    float2 w1 = make_float2(cs, sn);
    float2 w2 = cmulf(w1, w1);
    float2 w3 = cmulf(w2, w1);
    float2 w4 = cmulf(w2, w2);
    float2 w5 = cmulf(w3, w2);
    float2 w6 = cmulf(w3, w3);
    float2 w7 = cmulf(w4, w3);
    v[1] = cmulf(v[1], w1); v[2] = cmulf(v[2], w2);
    v[3] = cmulf(v[3], w3); v[4] = cmulf(v[4], w4);
    v[5] = cmulf(v[5], w5); v[6] = cmulf(v[6], w6);
    v[7] = cmulf(v[7], w7);
}

// one radix-8 pass in shared memory, stride H, sub-transform M=8H
template<int SGN, int H>
__device__ __forceinline__ void stage_sh(float2* s, int t)
{
    const int M = 8 * H;
    int base = (t / H) * M + (t % H);
    int a    = t % H;
    float2 v[8];
    #pragma unroll
    for (int i = 0; i < 8; i++)
        v[i] = s[SIDX(base + H * i)];
    if (SGN < 0) { dft8<SGN>(v); twiddles<SGN, M>(v, a); }
    else         { twiddles<SGN, M>(v, a); dft8<SGN>(v); }
    #pragma unroll
    for (int i = 0; i < 8; i++)
        s[SIDX(base + H * i)] = v[i];
}

// 64-thread named barrier: group = t>>6, ids 1..8 (id 0 = __syncthreads)
__device__ __forceinline__ void bar64(int t)
{
    asm volatile("bar.sync %0, 64;" :: "r"(1 + (t >> 6)) : "memory");
}

// ---------------- main kernel: 2 real channels per block ----------------
// Exchange granularity by construction:
//   st0 <-> stage64      : full block      -> __syncthreads
//   stage64 <-> stage8   : 64-thread group -> bar.sync id,64
//   stage8 <-> fused     : 8-thread group  -> __syncwarp
__global__ __launch_bounds__(TPB, 2)
void s4_fftconv_kernel(const float* __restrict__ x, float* __restrict__ y)
{
    __shared__ float2 s[LSEQ + (LSEQ >> 3)];
    const int t = threadIdx.x;
    const size_t base = (size_t)blockIdx.x * 2u * LSEQ;
    const float* x1 = x + base;
    const float* x2 = x + base + LSEQ;
    float* y1 = y + base;
    float* y2 = y + base + LSEQ;

    float2 v[8];

    // ---- forward stage 0 (M=4096, H=512): global -> regs -> shared
    #pragma unroll
    for (int b = 0; b < 8; b++)
        v[b] = make_float2(x1[t + 512 * b], x2[t + 512 * b]);
    dft8<-1>(v);
    twiddles<-1, 4096>(v, t);
    #pragma unroll
    for (int j = 0; j < 8; j++)
        s[SIDX(t + 512 * j)] = v[j];
    __syncthreads();

    stage_sh<-1, 64>(s, t);   // forward stage 1 (M=512)
    bar64(t);
    stage_sh<-1, 8>(s, t);    // forward stage 2 (M=64), within 64-blk (t>>3)
    __syncwarp();

    // ---- fused: fwd stage 3 (H=1) + Ksp + inv stage 3 — in regs,
    //      reads/writes 8 consecutive slots within 64-blk (t>>3)
    {
        const int p0 = SIDX(8 * t);       // 9t: 8 consecutive padded slots
        #pragma unroll
        for (int j = 0; j < 8; j++)
            v[j] = s[p0 + j];
        dft8<-1>(v);
        {   // Ksp as 4x LDG.128 (float4 = 2 complex)
            const float4* K4 = reinterpret_cast<const float4*>(g_Ksp) + 4 * t;
            #pragma unroll
            for (int q = 0; q < 4; q++) {
                float4 kk = __ldg(&K4[q]);
                v[2*q]   = cmulf(v[2*q],   make_float2(kk.x, kk.y));
                v[2*q+1] = cmulf(v[2*q+1], make_float2(kk.z, kk.w));
            }
        }
        dft8<1>(v);
        #pragma unroll
        for (int j = 0; j < 8; j++)
            s[p0 + j] = v[j];
    }
    __syncwarp();

    stage_sh<1, 8>(s, t);     // inverse stage 2
    bar64(t);
    stage_sh<1, 64>(s, t);    // inverse stage 1
    __syncthreads();

    // ---- inverse stage 0 (M=4096, H=512): shared -> regs -> global
    #pragma unroll
    for (int j = 0; j < 8; j++)
        v[j] = s[SIDX(t + 512 * j)];
    twiddles<1, 4096>(v, t);
    dft8<1>(v);
    #pragma unroll
    for (int b = 0; b < 8; b++) {
        y1[t + 512 * b] = v[b].x;
        y2[t + 512 * b] = v[b].y;
    }
}

extern "C" void kernel_launch(void* const* d_in, const int* in_sizes, int n_in,
                              void* d_out, int out_size)
{
    const float* x   = (const float*)d_in[0];
    const float* lre = (const float*)d_in[1];
    const float* lim = (const float*)d_in[2];
    const float* pre = (const float*)d_in[3];
    const float* pim = (const float*)d_in[4];
    const float* bre = (const float*)d_in[5];
    const float* bim = (const float*)d_in[6];
    const float* cre = (const float*)d_in[7];
    const float* cim = (const float*)d_in[8];
    float* y = (float*)d_out;

    compute_K_fused<<<(((LSEQ / 2 + 1) * 16) + 255) / 256, 256>>>(lre, lim, pre, pim, bre, bim, cre, cim);
    s4_fftconv_kernel<<<NPAIR, TPB>>>(x, y);
}

// round 7
// speedup vs baseline: 1.1984x; 1.0047x over previous
#include <cuda_runtime.h>
#include <math.h>

#define LSEQ   4096
#define NPAIR  2048      // 16*256/2
#define TPB    512

static __device__ float2 g_Ksp[LSEQ];

// base-8, 4-digit reversal
__device__ __forceinline__ int digitrev84(int i) {
    return ((i & 7) << 9) | (((i >> 3) & 7) << 6) |
           (((i >> 6) & 7) << 3) | ((i >> 9) & 7);
}

// ---------------- fused K + Ksp kernel (all fp32) ----------------
__global__ void compute_K_fused(const float* __restrict__ lre, const float* __restrict__ lim,
                                const float* __restrict__ pre, const float* __restrict__ pim,
                                const float* __restrict__ bre, const float* __restrict__ bim,
                                const float* __restrict__ cre, const float* __restrict__ cim)
{
    int gtid = blockIdx.x * blockDim.x + threadIdx.x;
    int k    = gtid >> 4;           // 0..2048
    int sub  = gtid & 15;
    if (k > LSEQ / 2) return;

    const float t = tanf((float)k * 7.6699039394282221e-4f);  // pi/4096
    const float G = 2000.0f * t;

    float a00r=0,a00i=0,a01r=0,a01i=0,a10r=0,a10i=0,a11r=0,a11i=0;
    float b00r=0,b00i=0,b01r=0,b01i=0,b10r=0,b10i=0,b11r=0,b11i=0;

    #pragma unroll
    for (int j = 0; j < 4; j++) {
        int n = sub * 4 + j;
        float lr = lre[n], li = lim[n];
        float pr = pre[n], pi_ = pim[n];
        float br = bre[n], bi = bim[n];
        float cr = cre[n], ci = cim[n];

        float nbr = fmaf(cr, br,  ci * bi),  nbi = fmaf(cr, bi, -ci * br);
        float npr = fmaf(cr, pr,  ci * pi_), npi = fmaf(cr, pi_, -ci * pr);
        float pbr = fmaf(pr, br,  pi_ * bi), pbi = fmaf(pr, bi, -pi_ * br);
        float pp  = fmaf(pr, pr,  pi_ * pi_);

        {
            float ex = -lr, ey = G - li;
            float r  = 1.0f / fmaf(ex, ex, ey * ey);
            float dr = ex * r, di = -ey * r;
            a00r = fmaf(dr, nbr, fmaf(-di, nbi, a00r));
            a00i = fmaf(dr, nbi, fmaf( di, nbr, a00i));
            a01r = fmaf(dr, npr, fmaf(-di, npi, a01r));
            a01i = fmaf(dr, npi, fmaf( di, npr, a01i));
            a10r = fmaf(dr, pbr, fmaf(-di, pbi, a10r));
            a10i = fmaf(dr, pbi, fmaf( di, pbr, a10i));
            a11r = fmaf(dr, pp, a11r);
            a11i = fmaf(di, pp, a11i);
        }
        {
            float ex = -lr, ey = -G - li;
            float r  = 1.0f / fmaf(ex, ex, ey * ey);
            float dr = ex * r, di = -ey * r;
            b00r = fmaf(dr, nbr, fmaf(-di, nbi, b00r));
            b00i = fmaf(dr, nbi, fmaf( di, nbr, b00i));
            b01r = fmaf(dr, npr, fmaf(-di, npi, b01r));
            b01i = fmaf(dr, npi, fmaf( di, npr, b01i));
            b10r = fmaf(dr, pbr, fmaf(-di, pbi, b10r));
            b10i = fmaf(dr, pbi, fmaf( di, pbr, b10i));
            b11r = fmaf(dr, pp, b11r);
            b11i = fmaf(di, pp, b11i);
        }
    }

    #pragma unroll
    for (int m = 1; m < 16; m <<= 1) {
        a00r += __shfl_xor_sync(0xffffffffu, a00r, m);
        a00i += __shfl_xor_sync(0xffffffffu, a00i, m);
        a01r += __shfl_xor_sync(0xffffffffu, a01r, m);
        a01i += __shfl_xor_sync(0xffffffffu, a01i, m);
        a10r += __shfl_xor_sync(0xffffffffu, a10r, m);
        a10i += __shfl_xor_sync(0xffffffffu, a10i, m);
        a11r += __shfl_xor_sync(0xffffffffu, a11r, m);
        a11i += __shfl_xor_sync(0xffffffffu, a11i, m);
        b00r += __shfl_xor_sync(0xffffffffu, b00r, m);
        b00i += __shfl_xor_sync(0xffffffffu, b00i, m);
        b01r += __shfl_xor_sync(0xffffffffu, b01r, m);
        b01i += __shfl_xor_sync(0xffffffffu, b01i, m);
        b10r += __shfl_xor_sync(0xffffffffu, b10r, m);
        b10i += __shfl_xor_sync(0xffffffffu, b10i, m);
        b11r += __shfl_xor_sync(0xffffffffu, b11r, m);
        b11i += __shfl_xor_sync(0xffffffffu, b11i, m);
    }

    if (sub == 0) {
        float Kk_r, Kk_i, Km_r, Km_i;
        {
            float numr = a01r * a10r - a01i * a10i;
            float numi = a01r * a10i + a01i * a10r;
            float der  = 1.0f + a11r, dei = a11i;
            float dd   = 1.0f / fmaf(der, der, dei * dei);
            float ar = a00r - (numr * der + numi * dei) * dd;
            float ai = a00i - (numi * der - numr * dei) * dd;
            Kk_r = fmaf(-t, ai, ar); Kk_i = fmaf(t, ar, ai);
        }
        {
            float numr = b01r * b10r - b01i * b10i;
            float numi = b01r * b10i + b01i * b10r;
            float der  = 1.0f + b11r, dei = b11i;
            float dd   = 1.0f / fmaf(der, der, dei * dei);
            float ar = b00r - (numr * der + numi * dei) * dd;
            float ai = b00i - (numi * der - numr * dei) * dd;
            Km_r = fmaf(t, ai, ar); Km_i = fmaf(-t, ar, ai);
        }
        const float sc = 0.5f / (float)LSEQ;
        float sr = (Kk_r + Km_r) * sc;
        float si = (Kk_i - Km_i) * sc;
        int mk = (LSEQ - k) & (LSEQ - 1);
        g_Ksp[digitrev84(k)]  = make_float2(sr,  si);
        g_Ksp[digitrev84(mk)] = make_float2(sr, -si);
    }
}

// ---------------- fp32 FFT machinery ----------------
#define SIDX(i) ((i) + ((i) >> 3))   // pad 1 per 8 complex

__device__ __forceinline__ float2 f2add(float2 a, float2 b){ return make_float2(a.x+b.x, a.y+b.y); }
__device__ __forceinline__ float2 f2sub(float2 a, float2 b){ return make_float2(a.x-b.x, a.y-b.y); }
__device__ __forceinline__ float2 cmulf(float2 a, float2 b){
    return make_float2(fmaf(a.x, b.x, -a.y*b.y), fmaf(a.x, b.y, a.y*b.x));
}
template<int SGN>
__device__ __forceinline__ float2 mul_is(float2 z){  // z * (i*SGN)
    return (SGN > 0) ? make_float2(-z.y, z.x) : make_float2(z.y, -z.x);
}

template<int SGN>
__device__ __forceinline__ void dft8(float2* v)
{
    const float C = 0.70710678118654752440f;
    const float S = (float)SGN;
    float2 u0 = f2add(v[0], v[4]), w0 = f2sub(v[0], v[4]);
    float2 u1 = f2add(v[1], v[5]), w1 = f2sub(v[1], v[5]);
    float2 u2 = f2add(v[2], v[6]), w2 = f2sub(v[2], v[6]);
    float2 u3 = f2add(v[3], v[7]), w3 = f2sub(v[3], v[7]);
    w1 = make_float2(C * (w1.x - S * w1.y),  C * (S * w1.x + w1.y));
    w2 = mul_is<SGN>(w2);
    w3 = make_float2(-C * (w3.x + S * w3.y), C * (S * w3.x - w3.y));
    float2 p0 = f2add(u0, u2), q0 = f2sub(u0, u2);
    float2 p1 = f2add(u1, u3), q1 = mul_is<SGN>(f2sub(u1, u3));
    v[0] = f2add(p0, p1); v[4] = f2sub(p0, p1);
    v[2] = f2add(q0, q1); v[6] = f2sub(q0, q1);
    float2 r0 = f2add(w0, w2), s0 = f2sub(w0, w2);
    float2 r1 = f2add(w1, w3), s1 = mul_is<SGN>(f2sub(w1, w3));
    v[1] = f2add(r0, r1); v[5] = f2sub(r0, r1);
    v[3] = f2add(s0, s1); v[7] = f2sub(s0, s1);
}

// apply w_M^(SGN*a*j) to v[j], j=1..7 — powers via depth-3 tree
template<int SGN, int M>
__device__ __forceinline__ void twiddles(float2* v, int a)
{
    const float kAng = (float)SGN * 6.283185307179586f / (float)M;
    float sn, cs;
    __sincosf(kAng * (float)a, &sn, &cs);
    float2 w1 = make_float2(cs, sn);
    float2 w2 = cmulf(w1, w1);
    float2 w3 = cmulf(w2, w1);
    float2 w4 = cmulf(w2, w2);
    float2 w5 = cmulf(w3, w2);
    float2 w6 = cmulf(w3, w3);
    float2 w7 = cmulf(w4, w3);
    v[1] = cmulf(v[1], w1); v[2] = cmulf(v[2], w2);
    v[3] = cmulf(v[3], w3); v[4] = cmulf(v[4], w4);
    v[5] = cmulf(v[5], w5); v[6] = cmulf(v[6], w6);
    v[7] = cmulf(v[7], w7);
}

// 8x8 transpose across 8 lanes (lane index a = t&7), 8 float2 regs.
__device__ __forceinline__ void transpose8(float2* v, int a)
{
    #pragma unroll
    for (int k = 1; k < 8; k <<= 1) {
        bool up = (a & k) != 0;
        #pragma unroll
        for (int j0 = 0; j0 < 8; j0++) {
            if ((j0 & k) == 0) {
                int j1 = j0 | k;
                float sx = up ? v[j0].x : v[j1].x;
                float sy = up ? v[j0].y : v[j1].y;
                sx = __shfl_xor_sync(0xffffffffu, sx, k);
                sy = __shfl_xor_sync(0xffffffffu, sy, k);
                if (up) { v[j0].x = sx; v[j0].y = sy; }
                else    { v[j1].x = sx; v[j1].y = sy; }
            }
        }
    }
}

// one radix-8 pass in shared memory, stride H, sub-transform M=8H
template<int SGN, int H>
__device__ __forceinline__ void stage_sh(float2* s, int t)
{
    const int M = 8 * H;
    int base = (t / H) * M + (t % H);
    int a    = t % H;
    float2 v[8];
    #pragma unroll
    for (int i = 0; i < 8; i++)
        v[i] = s[SIDX(base + H * i)];
    if (SGN < 0) { dft8<SGN>(v); twiddles<SGN, M>(v, a); }
    else         { twiddles<SGN, M>(v, a); dft8<SGN>(v); }
    #pragma unroll
    for (int i = 0; i < 8; i++)
        s[SIDX(base + H * i)] = v[i];
}

// 64-thread named barrier: group = t>>6, ids 1..8
__device__ __forceinline__ void bar64(int t)
{
    asm volatile("bar.sync %0, 64;" :: "r"(1 + (t >> 6)) : "memory");
}

// ---------------- main kernel: 2 real channels per block ----------------
// Barrier map:
//   st0 <-> stage64               : __syncthreads (global mixing)
//   stage64 <-> merged middle     : bar.sync id,64 (64-thread groups)
//   inside merged middle          : shfl-only (8-lane groups) — no barrier
__global__ __launch_bounds__(TPB, 2)
void s4_fftconv_kernel(const float* __restrict__ x, float* __restrict__ y)
{
    __shared__ float2 s[LSEQ + (LSEQ >> 3)];
    const int t = threadIdx.x;
    const size_t base = (size_t)blockIdx.x * 2u * LSEQ;
    const float* x1 = x + base;
    const float* x2 = x + base + LSEQ;
    float* y1 = y + base;
    float* y2 = y + base + LSEQ;

    float2 v[8];

    // ---- forward stage 0 (M=4096, H=512): global -> regs -> shared
    #pragma unroll
    for (int b = 0; b < 8; b++)
        v[b] = make_float2(x1[t + 512 * b], x2[t + 512 * b]);
    dft8<-1>(v);
    twiddles<-1, 4096>(v, t);
    #pragma unroll
    for (int j = 0; j < 8; j++)
        s[SIDX(t + 512 * j)] = v[j];
    __syncthreads();

    stage_sh<-1, 64>(s, t);   // forward stage 1 (M=512, H=64)
    bar64(t);

    // ---- merged middle: fwd H=8 + transpose + fwd H=1 + Ksp + inv H=1 +
    //      transpose + inv H=8 — one smem round trip, all intra-warp
    {
        const int g = t >> 3;
        const int a = t & 7;
        const int mbase = 64 * g + a;
        #pragma unroll
        for (int i = 0; i < 8; i++)
            v[i] = s[SIDX(mbase + 8 * i)];
        // prefetch Ksp (independent of v; overlaps the butterfly chain)
        float4 kk0, kk1, kk2, kk3;
        {
            const float4* K4 = reinterpret_cast<const float4*>(g_Ksp) + 4 * t;
            kk0 = __ldg(&K4[0]); kk1 = __ldg(&K4[1]);
            kk2 = __ldg(&K4[2]); kk3 = __ldg(&K4[3]);
        }
        dft8<-1>(v);
        twiddles<-1, 64>(v, a);
        transpose8(v, a);                 // v[d] = element 64g + 8a + d = 8t + d
        dft8<-1>(v);                      // fwd H=1 (no twiddle)
        v[0] = cmulf(v[0], make_float2(kk0.x, kk0.y));
        v[1] = cmulf(v[1], make_float2(kk0.z, kk0.w));
        v[2] = cmulf(v[2], make_float2(kk1.x, kk1.y));
        v[3] = cmulf(v[3], make_float2(kk1.z, kk1.w));
        v[4] = cmulf(v[4], make_float2(kk2.x, kk2.y));
        v[5] = cmulf(v[5], make_float2(kk2.z, kk2.w));
        v[6] = cmulf(v[6], make_float2(kk3.x, kk3.y));
        v[7] = cmulf(v[7], make_float2(kk3.z, kk3.w));
        dft8<1>(v);                       // inverse H=1
        transpose8(v, a);
        twiddles<1, 64>(v, a);
        dft8<1>(v);                       // inverse H=8
        #pragma unroll
        for (int i = 0; i < 8; i++)
            s[SIDX(mbase + 8 * i)] = v[i];
    }
    bar64(t);

    stage_sh<1, 64>(s, t);    // inverse stage 1
    __syncthreads();

    // ---- inverse stage 0 (M=4096, H=512): shared -> regs -> global
    #pragma unroll
    for (int j = 0; j < 8; j++)
        v[j] = s[SIDX(t + 512 * j)];
    twiddles<1, 4096>(v, t);
    dft8<1>(v);
    #pragma unroll
    for (int b = 0; b < 8; b++) {
        y1[t + 512 * b] = v[b].x;
        y2[t + 512 * b] = v[b].y;
    }
}

extern "C" void kernel_launch(void* const* d_in, const int* in_sizes, int n_in,
                              void* d_out, int out_size)
{
    const float* x   = (const float*)d_in[0];
    const float* lre = (const float*)d_in[1];
    const float* lim = (const float*)d_in[2];
    const float* pre = (const float*)d_in[3];
    const float* pim = (const float*)d_in[4];
    const float* bre = (const float*)d_in[5];
    const float* bim = (const float*)d_in[6];
    const float* cre = (const float*)d_in[7];
    const float* cim = (const float*)d_in[8];
    float* y = (float*)d_out;

    compute_K_fused<<<(((LSEQ / 2 + 1) * 16) + 255) / 256, 256>>>(lre, lim, pre, pim, bre, bim, cre, cim);
    s4_fftconv_kernel<<<NPAIR, TPB>>>(x, y);
}

// round 8
// speedup vs baseline: 1.2180x; 1.0163x over previous
#include <cuda_runtime.h>
#include <math.h>

#define LSEQ   4096
#define NPAIR  2048      // 16*256/2
#define TPB    512

static __device__ float2 g_Ksp[LSEQ];

// base-8, 4-digit reversal
__device__ __forceinline__ int digitrev84(int i) {
    return ((i & 7) << 9) | (((i >> 3) & 7) << 6) |
           (((i >> 6) & 7) << 3) | ((i >> 9) & 7);
}

// ---------------- fused K + Ksp kernel (all fp32) ----------------
__global__ void compute_K_fused(const float* __restrict__ lre, const float* __restrict__ lim,
                                const float* __restrict__ pre, const float* __restrict__ pim,
                                const float* __restrict__ bre, const float* __restrict__ bim,
                                const float* __restrict__ cre, const float* __restrict__ cim)
{
    int gtid = blockIdx.x * blockDim.x + threadIdx.x;
    int k    = gtid >> 4;           // 0..2048
    int sub  = gtid & 15;
    if (k > LSEQ / 2) return;

    const float t = tanf((float)k * 7.6699039394282221e-4f);  // pi/4096
    const float G = 2000.0f * t;

    float a00r=0,a00i=0,a01r=0,a01i=0,a10r=0,a10i=0,a11r=0,a11i=0;
    float b00r=0,b00i=0,b01r=0,b01i=0,b10r=0,b10i=0,b11r=0,b11i=0;

    #pragma unroll
    for (int j = 0; j < 4; j++) {
        int n = sub * 4 + j;
        float lr = lre[n], li = lim[n];
        float pr = pre[n], pi_ = pim[n];
        float br = bre[n], bi = bim[n];
        float cr = cre[n], ci = cim[n];

        float nbr = fmaf(cr, br,  ci * bi),  nbi = fmaf(cr, bi, -ci * br);
        float npr = fmaf(cr, pr,  ci * pi_), npi = fmaf(cr, pi_, -ci * pr);
        float pbr = fmaf(pr, br,  pi_ * bi), pbi = fmaf(pr, bi, -pi_ * br);
        float pp  = fmaf(pr, pr,  pi_ * pi_);

        {
            float ex = -lr, ey = G - li;
            float r  = 1.0f / fmaf(ex, ex, ey * ey);
            float dr = ex * r, di = -ey * r;
            a00r = fmaf(dr, nbr, fmaf(-di, nbi, a00r));
            a00i = fmaf(dr, nbi, fmaf( di, nbr, a00i));
            a01r = fmaf(dr, npr, fmaf(-di, npi, a01r));
            a01i = fmaf(dr, npi, fmaf( di, npr, a01i));
            a10r = fmaf(dr, pbr, fmaf(-di, pbi, a10r));
            a10i = fmaf(dr, pbi, fmaf( di, pbr, a10i));
            a11r = fmaf(dr, pp, a11r);
            a11i = fmaf(di, pp, a11i);
        }
        {
            float ex = -lr, ey = -G - li;
            float r  = 1.0f / fmaf(ex, ex, ey * ey);
            float dr = ex * r, di = -ey * r;
            b00r = fmaf(dr, nbr, fmaf(-di, nbi, b00r));
            b00i = fmaf(dr, nbi, fmaf( di, nbr, b00i));
            b01r = fmaf(dr, npr, fmaf(-di, npi, b01r));
            b01i = fmaf(dr, npi, fmaf( di, npr, b01i));
            b10r = fmaf(dr, pbr, fmaf(-di, pbi, b10r));
            b10i = fmaf(dr, pbi, fmaf( di, pbr, b10i));
            b11r = fmaf(dr, pp, b11r);
            b11i = fmaf(di, pp, b11i);
        }
    }

    #pragma unroll
    for (int m = 1; m < 16; m <<= 1) {
        a00r += __shfl_xor_sync(0xffffffffu, a00r, m);
        a00i += __shfl_xor_sync(0xffffffffu, a00i, m);
        a01r += __shfl_xor_sync(0xffffffffu, a01r, m);
        a01i += __shfl_xor_sync(0xffffffffu, a01i, m);
        a10r += __shfl_xor_sync(0xffffffffu, a10r, m);
        a10i += __shfl_xor_sync(0xffffffffu, a10i, m);
        a11r += __shfl_xor_sync(0xffffffffu, a11r, m);
        a11i += __shfl_xor_sync(0xffffffffu, a11i, m);
        b00r += __shfl_xor_sync(0xffffffffu, b00r, m);
        b00i += __shfl_xor_sync(0xffffffffu, b00i, m);
        b01r += __shfl_xor_sync(0xffffffffu, b01r, m);
        b01i += __shfl_xor_sync(0xffffffffu, b01i, m);
        b10r += __shfl_xor_sync(0xffffffffu, b10r, m);
        b10i += __shfl_xor_sync(0xffffffffu, b10i, m);
        b11r += __shfl_xor_sync(0xffffffffu, b11r, m);
        b11i += __shfl_xor_sync(0xffffffffu, b11i, m);
    }

    if (sub == 0) {
        float Kk_r, Kk_i, Km_r, Km_i;
        {
            float numr = a01r * a10r - a01i * a10i;
            float numi = a01r * a10i + a01i * a10r;
            float der  = 1.0f + a11r, dei = a11i;
            float dd   = 1.0f / fmaf(der, der, dei * dei);
            float ar = a00r - (numr * der + numi * dei) * dd;
            float ai = a00i - (numi * der - numr * dei) * dd;
            Kk_r = fmaf(-t, ai, ar); Kk_i = fmaf(t, ar, ai);
        }
        {
            float numr = b01r * b10r - b01i * b10i;
            float numi = b01r * b10i + b01i * b10r;
            float der  = 1.0f + b11r, dei = b11i;
            float dd   = 1.0f / fmaf(der, der, dei * dei);
            float ar = b00r - (numr * der + numi * dei) * dd;
            float ai = b00i - (numi * der - numr * dei) * dd;
            Km_r = fmaf(t, ai, ar); Km_i = fmaf(-t, ar, ai);
        }
        const float sc = 0.5f / (float)LSEQ;
        float sr = (Kk_r + Km_r) * sc;
        float si = (Kk_i - Km_i) * sc;
        int mk = (LSEQ - k) & (LSEQ - 1);
        g_Ksp[digitrev84(k)]  = make_float2(sr,  si);
        g_Ksp[digitrev84(mk)] = make_float2(sr, -si);
    }
}

// ---------------- fp32 FFT machinery ----------------
#define SIDX(i) ((i) + ((i) >> 3))   // pad 1 per 8 complex

// Packed f32x2 complex add/sub (Blackwell FADD2/FFMA2 — ptxas never emits
// these from scalar C++; only reachable via PTX f32x2 ops).
__device__ __forceinline__ float2 f2add(float2 a, float2 b){
    float2 r;
    asm("{\n\t"
        ".reg .b64 ra, rb, rc;\n\t"
        "mov.b64 ra, {%2, %3};\n\t"
        "mov.b64 rb, {%4, %5};\n\t"
        "add.rn.f32x2 rc, ra, rb;\n\t"
        "mov.b64 {%0, %1}, rc;\n\t"
        "}"
        : "=f"(r.x), "=f"(r.y)
        : "f"(a.x), "f"(a.y), "f"(b.x), "f"(b.y));
    return r;
}
// a - b  ==  fma(b, (-1,-1), a)
__device__ __forceinline__ float2 f2sub(float2 a, float2 b){
    float2 r;
    asm("{\n\t"
        ".reg .b64 ra, rb, rc, rn;\n\t"
        "mov.b64 rn, 0xBF800000BF800000;\n\t"
        "mov.b64 ra, {%2, %3};\n\t"
        "mov.b64 rb, {%4, %5};\n\t"
        "fma.rn.f32x2 rc, rb, rn, ra;\n\t"
        "mov.b64 {%0, %1}, rc;\n\t"
        "}"
        : "=f"(r.x), "=f"(r.y)
        : "f"(a.x), "f"(a.y), "f"(b.x), "f"(b.y));
    return r;
}

__device__ __forceinline__ float2 cmulf(float2 a, float2 b){
    return make_float2(fmaf(a.x, b.x, -a.y*b.y), fmaf(a.x, b.y, a.y*b.x));
}

// radix-8 DFT, natural order, unscaled. Pure add/subs go through packed
// f32x2; the +-i cross-component combines stay scalar (free sign folding).
template<int SGN>
__device__ __forceinline__ void dft8(float2* v)
{
    const float C = 0.70710678118654752440f;
    const float S = (float)SGN;
    float2 u0 = f2add(v[0], v[4]), w0 = f2sub(v[0], v[4]);
    float2 u1 = f2add(v[1], v[5]), w1 = f2sub(v[1], v[5]);
    float2 u2 = f2add(v[2], v[6]), w2 = f2sub(v[2], v[6]);
    float2 u3 = f2add(v[3], v[7]), w3 = f2sub(v[3], v[7]);
    // odd-branch rotations (scalar)
    w1 = make_float2(C * (w1.x - S * w1.y),  C * (S * w1.x + w1.y));
    w3 = make_float2(-C * (w3.x + S * w3.y), C * (S * w3.x - w3.y));
    // even 4-pt
    float2 p0 = f2add(u0, u2), q0 = f2sub(u0, u2);
    float2 p1 = f2add(u1, u3), t1 = f2sub(u1, u3);
    v[0] = f2add(p0, p1); v[4] = f2sub(p0, p1);
    v[2] = make_float2(q0.x - S * t1.y, q0.y + S * t1.x);   // q0 + iS*t1
    v[6] = make_float2(q0.x + S * t1.y, q0.y - S * t1.x);   // q0 - iS*t1
    // odd 4-pt: r0 = w0 + iS*w2, s0 = w0 - iS*w2 (scalar cross)
    float2 r0 = make_float2(w0.x - S * w2.y, w0.y + S * w2.x);
    float2 s0 = make_float2(w0.x + S * w2.y, w0.y - S * w2.x);
    float2 r1 = f2add(w1, w3), t2 = f2sub(w1, w3);
    v[1] = f2add(r0, r1); v[5] = f2sub(r0, r1);
    v[3] = make_float2(s0.x - S * t2.y, s0.y + S * t2.x);   // s0 + iS*t2
    v[7] = make_float2(s0.x + S * t2.y, s0.y - S * t2.x);   // s0 - iS*t2
}

// apply w_M^(SGN*a*j) to v[j], j=1..7 — powers via depth-3 tree
template<int SGN, int M>
__device__ __forceinline__ void twiddles(float2* v, int a)
{
    const float kAng = (float)SGN * 6.283185307179586f / (float)M;
    float sn, cs;
    __sincosf(kAng * (float)a, &sn, &cs);
    float2 w1 = make_float2(cs, sn);
    float2 w2 = cmulf(w1, w1);
    float2 w3 = cmulf(w2, w1);
    float2 w4 = cmulf(w2, w2);
    float2 w5 = cmulf(w3, w2);
    float2 w6 = cmulf(w3, w3);
    float2 w7 = cmulf(w4, w3);
    v[1] = cmulf(v[1], w1); v[2] = cmulf(v[2], w2);
    v[3] = cmulf(v[3], w3); v[4] = cmulf(v[4], w4);
    v[5] = cmulf(v[5], w5); v[6] = cmulf(v[6], w6);
    v[7] = cmulf(v[7], w7);
}

// 8x8 transpose across 8 lanes (lane index a = t&7), 8 float2 regs.
__device__ __forceinline__ void transpose8(float2* v, int a)
{
    #pragma unroll
    for (int k = 1; k < 8; k <<= 1) {
        bool up = (a & k) != 0;
        #pragma unroll
        for (int j0 = 0; j0 < 8; j0++) {
            if ((j0 & k) == 0) {
                int j1 = j0 | k;
                float sx = up ? v[j0].x : v[j1].x;
                float sy = up ? v[j0].y : v[j1].y;
                sx = __shfl_xor_sync(0xffffffffu, sx, k);
                sy = __shfl_xor_sync(0xffffffffu, sy, k);
                if (up) { v[j0].x = sx; v[j0].y = sy; }
                else    { v[j1].x = sx; v[j1].y = sy; }
            }
        }
    }
}

// one radix-8 pass in shared memory, stride H, sub-transform M=8H
template<int SGN, int H>
__device__ __forceinline__ void stage_sh(float2* s, int t)
{
    const int M = 8 * H;
    int base = (t / H) * M + (t % H);
    int a    = t % H;
    float2 v[8];
    #pragma unroll
    for (int i = 0; i < 8; i++)
        v[i] = s[SIDX(base + H * i)];
    if (SGN < 0) { dft8<SGN>(v); twiddles<SGN, M>(v, a); }
    else         { twiddles<SGN, M>(v, a); dft8<SGN>(v); }
    #pragma unroll
    for (int i = 0; i < 8; i++)
        s[SIDX(base + H * i)] = v[i];
}

// 64-thread named barrier: group = t>>6, ids 1..8
__device__ __forceinline__ void bar64(int t)
{
    asm volatile("bar.sync %0, 64;" :: "r"(1 + (t >> 6)) : "memory");
}

// ---------------- main kernel: 2 real channels per block ----------------
__global__ __launch_bounds__(TPB, 2)
void s4_fftconv_kernel(const float* __restrict__ x, float* __restrict__ y)
{
    __shared__ float2 s[LSEQ + (LSEQ >> 3)];
    const int t = threadIdx.x;
    const size_t base = (size_t)blockIdx.x * 2u * LSEQ;
    const float* x1 = x + base;
    const float* x2 = x + base + LSEQ;
    float* y1 = y + base;
    float* y2 = y + base + LSEQ;

    float2 v[8];

    // ---- forward stage 0 (M=4096, H=512): global -> regs -> shared
    #pragma unroll
    for (int b = 0; b < 8; b++)
        v[b] = make_float2(x1[t + 512 * b], x2[t + 512 * b]);
    dft8<-1>(v);
    twiddles<-1, 4096>(v, t);
    #pragma unroll
    for (int j = 0; j < 8; j++)
        s[SIDX(t + 512 * j)] = v[j];
    __syncthreads();

    stage_sh<-1, 64>(s, t);   // forward stage 1 (M=512, H=64)
    bar64(t);

    // ---- merged middle: fwd H=8 + transpose + fwd H=1 + Ksp + inv H=1 +
    //      transpose + inv H=8 — one smem round trip, all intra-warp
    {
        const int g = t >> 3;
        const int a = t & 7;
        const int mbase = 64 * g + a;
        #pragma unroll
        for (int i = 0; i < 8; i++)
            v[i] = s[SIDX(mbase + 8 * i)];
        // prefetch Ksp (independent of v; overlaps the butterfly chain)
        float4 kk0, kk1, kk2, kk3;
        {
            const float4* K4 = reinterpret_cast<const float4*>(g_Ksp) + 4 * t;
            kk0 = __ldg(&K4[0]); kk1 = __ldg(&K4[1]);
            kk2 = __ldg(&K4[2]); kk3 = __ldg(&K4[3]);
        }
        dft8<-1>(v);
        twiddles<-1, 64>(v, a);
        transpose8(v, a);                 // v[d] = element 64g + 8a + d = 8t + d
        dft8<-1>(v);                      // fwd H=1 (no twiddle)
        v[0] = cmulf(v[0], make_float2(kk0.x, kk0.y));
        v[1] = cmulf(v[1], make_float2(kk0.z, kk0.w));
        v[2] = cmulf(v[2], make_float2(kk1.x, kk1.y));
        v[3] = cmulf(v[3], make_float2(kk1.z, kk1.w));
        v[4] = cmulf(v[4], make_float2(kk2.x, kk2.y));
        v[5] = cmulf(v[5], make_float2(kk2.z, kk2.w));
        v[6] = cmulf(v[6], make_float2(kk3.x, kk3.y));
        v[7] = cmulf(v[7], make_float2(kk3.z, kk3.w));
        dft8<1>(v);                       // inverse H=1
        transpose8(v, a);
        twiddles<1, 64>(v, a);
        dft8<1>(v);                       // inverse H=8
        #pragma unroll
        for (int i = 0; i < 8; i++)
            s[SIDX(mbase + 8 * i)] = v[i];
    }
    bar64(t);

    stage_sh<1, 64>(s, t);    // inverse stage 1
    __syncthreads();

    // ---- inverse stage 0 (M=4096, H=512): shared -> regs -> global
    #pragma unroll
    for (int j = 0; j < 8; j++)
        v[j] = s[SIDX(t + 512 * j)];
    twiddles<1, 4096>(v, t);
    dft8<1>(v);
    #pragma unroll
    for (int b = 0; b < 8; b++) {
        y1[t + 512 * b] = v[b].x;
        y2[t + 512 * b] = v[b].y;
    }
}

extern "C" void kernel_launch(void* const* d_in, const int* in_sizes, int n_in,
                              void* d_out, int out_size)
{
    const float* x   = (const float*)d_in[0];
    const float* lre = (const float*)d_in[1];
    const float* lim = (const float*)d_in[2];
    const float* pre = (const float*)d_in[3];
    const float* pim = (const float*)d_in[4];
    const float* bre = (const float*)d_in[5];
    const float* bim = (const float*)d_in[6];
    const float* cre = (const float*)d_in[7];
    const float* cim = (const float*)d_in[8];
    float* y = (float*)d_out;

    compute_K_fused<<<(((LSEQ / 2 + 1) * 16) + 255) / 256, 256>>>(lre, lim, pre, pim, bre, bim, cre, cim);
    s4_fftconv_kernel<<<NPAIR, TPB>>>(x, y);
}

// round 9
// speedup vs baseline: 1.3305x; 1.0924x over previous
#include <cuda_runtime.h>
#include <math.h>

#define LSEQ   4096
#define NPAIR  2048      // 16*256/2
#define TPB    512

static __device__ float2 g_Ksp[LSEQ];

// base-8, 4-digit reversal
__device__ __forceinline__ int digitrev84(int i) {
    return ((i & 7) << 9) | (((i >> 3) & 7) << 6) |
           (((i >> 6) & 7) << 3) | ((i >> 9) & 7);
}

// ---------------- fused K + Ksp kernel (all fp32) ----------------
// 4 lanes per k, 16 states per lane; each group handles k and mirror L-k.
__global__ void compute_K_fused(const float* __restrict__ lre, const float* __restrict__ lim,
                                const float* __restrict__ pre, const float* __restrict__ pim,
                                const float* __restrict__ bre, const float* __restrict__ bim,
                                const float* __restrict__ cre, const float* __restrict__ cim)
{
    int gtid = blockIdx.x * blockDim.x + threadIdx.x;
    int k    = gtid >> 2;           // 0..2048
    int sub  = gtid & 3;
    if (k > LSEQ / 2) return;

    const float t = tanf((float)k * 7.6699039394282221e-4f);  // pi/4096
    const float G = 2000.0f * t;

    float a00r=0,a00i=0,a01r=0,a01i=0,a10r=0,a10i=0,a11r=0,a11i=0;
    float b00r=0,b00i=0,b01r=0,b01i=0,b10r=0,b10i=0,b11r=0,b11i=0;

    #pragma unroll
    for (int j = 0; j < 16; j++) {
        int n = sub * 16 + j;
        float lr = lre[n], li = lim[n];
        float pr = pre[n], pi_ = pim[n];
        float br = bre[n], bi = bim[n];
        float cr = cre[n], ci = cim[n];

        float nbr = fmaf(cr, br,  ci * bi),  nbi = fmaf(cr, bi, -ci * br);
        float npr = fmaf(cr, pr,  ci * pi_), npi = fmaf(cr, pi_, -ci * pr);
        float pbr = fmaf(pr, br,  pi_ * bi), pbi = fmaf(pr, bi, -pi_ * br);
        float pp  = fmaf(pr, pr,  pi_ * pi_);

        {
            float ex = -lr, ey = G - li;
            float r  = 1.0f / fmaf(ex, ex, ey * ey);
            float dr = ex * r, di = -ey * r;
            a00r = fmaf(dr, nbr, fmaf(-di, nbi, a00r));
            a00i = fmaf(dr, nbi, fmaf( di, nbr, a00i));
            a01r = fmaf(dr, npr, fmaf(-di, npi, a01r));
            a01i = fmaf(dr, npi, fmaf( di, npr, a01i));
            a10r = fmaf(dr, pbr, fmaf(-di, pbi, a10r));
            a10i = fmaf(dr, pbi, fmaf( di, pbr, a10i));
            a11r = fmaf(dr, pp, a11r);
            a11i = fmaf(di, pp, a11i);
        }
        {
            float ex = -lr, ey = -G - li;
            float r  = 1.0f / fmaf(ex, ex, ey * ey);
            float dr = ex * r, di = -ey * r;
            b00r = fmaf(dr, nbr, fmaf(-di, nbi, b00r));
            b00i = fmaf(dr, nbi, fmaf( di, nbr, b00i));
            b01r = fmaf(dr, npr, fmaf(-di, npi, b01r));
            b01i = fmaf(dr, npi, fmaf( di, npr, b01i));
            b10r = fmaf(dr, pbr, fmaf(-di, pbi, b10r));
            b10i = fmaf(dr, pbi, fmaf( di, pbr, b10i));
            b11r = fmaf(dr, pp, b11r);
            b11i = fmaf(di, pp, b11i);
        }
    }

    #pragma unroll
    for (int m = 1; m < 4; m <<= 1) {
        a00r += __shfl_xor_sync(0xffffffffu, a00r, m);
        a00i += __shfl_xor_sync(0xffffffffu, a00i, m);
        a01r += __shfl_xor_sync(0xffffffffu, a01r, m);
        a01i += __shfl_xor_sync(0xffffffffu, a01i, m);
        a10r += __shfl_xor_sync(0xffffffffu, a10r, m);
        a10i += __shfl_xor_sync(0xffffffffu, a10i, m);
        a11r += __shfl_xor_sync(0xffffffffu, a11r, m);
        a11i += __shfl_xor_sync(0xffffffffu, a11i, m);
        b00r += __shfl_xor_sync(0xffffffffu, b00r, m);
        b00i += __shfl_xor_sync(0xffffffffu, b00i, m);
        b01r += __shfl_xor_sync(0xffffffffu, b01r, m);
        b01i += __shfl_xor_sync(0xffffffffu, b01i, m);
        b10r += __shfl_xor_sync(0xffffffffu, b10r, m);
        b10i += __shfl_xor_sync(0xffffffffu, b10i, m);
        b11r += __shfl_xor_sync(0xffffffffu, b11r, m);
        b11i += __shfl_xor_sync(0xffffffffu, b11i, m);
    }

    if (sub == 0) {
        float Kk_r, Kk_i, Km_r, Km_i;
        {
            float numr = a01r * a10r - a01i * a10i;
            float numi = a01r * a10i + a01i * a10r;
            float der  = 1.0f + a11r, dei = a11i;
            float dd   = 1.0f / fmaf(der, der, dei * dei);
            float ar = a00r - (numr * der + numi * dei) * dd;
            float ai = a00i - (numi * der - numr * dei) * dd;
            Kk_r = fmaf(-t, ai, ar); Kk_i = fmaf(t, ar, ai);
        }
        {
            float numr = b01r * b10r - b01i * b10i;
            float numi = b01r * b10i + b01i * b10r;
            float der  = 1.0f + b11r, dei = b11i;
            float dd   = 1.0f / fmaf(der, der, dei * dei);
            float ar = b00r - (numr * der + numi * dei) * dd;
            float ai = b00i - (numi * der - numr * dei) * dd;
            Km_r = fmaf(t, ai, ar); Km_i = fmaf(-t, ar, ai);
        }
        const float sc = 0.5f / (float)LSEQ;
        float sr = (Kk_r + Km_r) * sc;
        float si = (Kk_i - Km_i) * sc;
        int mk = (LSEQ - k) & (LSEQ - 1);
        g_Ksp[digitrev84(k)]  = make_float2(sr,  si);
        g_Ksp[digitrev84(mk)] = make_float2(sr, -si);
    }
}

// ---------------- fp32 FFT machinery ----------------
// XOR swizzle: conflict-free for stride-512, stride-64 and stride-8 phases.
#define SWZ(i) ((i) ^ (((i) >> 3) & 0x38))

// Packed f32x2 complex add/sub (Blackwell FADD2/FFMA2).
__device__ __forceinline__ float2 f2add(float2 a, float2 b){
    float2 r;
    asm("{\n\t"
        ".reg .b64 ra, rb, rc;\n\t"
        "mov.b64 ra, {%2, %3};\n\t"
        "mov.b64 rb, {%4, %5};\n\t"
        "add.rn.f32x2 rc, ra, rb;\n\t"
        "mov.b64 {%0, %1}, rc;\n\t"
        "}"
        : "=f"(r.x), "=f"(r.y)
        : "f"(a.x), "f"(a.y), "f"(b.x), "f"(b.y));
    return r;
}
__device__ __forceinline__ float2 f2sub(float2 a, float2 b){
    float2 r;
    asm("{\n\t"
        ".reg .b64 ra, rb, rc, rn;\n\t"
        "mov.b64 rn, 0xBF800000BF800000;\n\t"
        "mov.b64 ra, {%2, %3};\n\t"
        "mov.b64 rb, {%4, %5};\n\t"
        "fma.rn.f32x2 rc, rb, rn, ra;\n\t"
        "mov.b64 {%0, %1}, rc;\n\t"
        "}"
        : "=f"(r.x), "=f"(r.y)
        : "f"(a.x), "f"(a.y), "f"(b.x), "f"(b.y));
    return r;
}

__device__ __forceinline__ float2 cmulf(float2 a, float2 b){
    return make_float2(fmaf(a.x, b.x, -a.y*b.y), fmaf(a.x, b.y, a.y*b.x));
}

// radix-8 DFT, natural order, unscaled; add/subs packed, cross terms scalar.
template<int SGN>
__device__ __forceinline__ void dft8(float2* v)
{
    const float C = 0.70710678118654752440f;
    const float S = (float)SGN;
    float2 u0 = f2add(v[0], v[4]), w0 = f2sub(v[0], v[4]);
    float2 u1 = f2add(v[1], v[5]), w1 = f2sub(v[1], v[5]);
    float2 u2 = f2add(v[2], v[6]), w2 = f2sub(v[2], v[6]);
    float2 u3 = f2add(v[3], v[7]), w3 = f2sub(v[3], v[7]);
    w1 = make_float2(C * (w1.x - S * w1.y),  C * (S * w1.x + w1.y));
    w3 = make_float2(-C * (w3.x + S * w3.y), C * (S * w3.x - w3.y));
    float2 p0 = f2add(u0, u2), q0 = f2sub(u0, u2);
    float2 p1 = f2add(u1, u3), t1 = f2sub(u1, u3);
    v[0] = f2add(p0, p1); v[4] = f2sub(p0, p1);
    v[2] = make_float2(q0.x - S * t1.y, q0.y + S * t1.x);
    v[6] = make_float2(q0.x + S * t1.y, q0.y - S * t1.x);
    float2 r0 = make_float2(w0.x - S * w2.y, w0.y + S * w2.x);
    float2 s0 = make_float2(w0.x + S * w2.y, w0.y - S * w2.x);
    float2 r1 = f2add(w1, w3), t2 = f2sub(w1, w3);
    v[1] = f2add(r0, r1); v[5] = f2sub(r0, r1);
    v[3] = make_float2(s0.x - S * t2.y, s0.y + S * t2.x);
    v[7] = make_float2(s0.x + S * t2.y, s0.y - S * t2.x);
}

// apply w_M^(SGN*a*j) to v[j], j=1..7 — powers via depth-3 tree
template<int SGN, int M>
__device__ __forceinline__ void twiddles(float2* v, int a)
{
    const float kAng = (float)SGN * 6.283185307179586f / (float)M;
    float sn, cs;
    __sincosf(kAng * (float)a, &sn, &cs);
    float2 w1 = make_float2(cs, sn);
    float2 w2 = cmulf(w1, w1);
    float2 w3 = cmulf(w2, w1);
    float2 w4 = cmulf(w2, w2);
    float2 w5 = cmulf(w3, w2);
    float2 w6 = cmulf(w3, w3);
    float2 w7 = cmulf(w4, w3);
    v[1] = cmulf(v[1], w1); v[2] = cmulf(v[2], w2);
    v[3] = cmulf(v[3], w3); v[4] = cmulf(v[4], w4);
    v[5] = cmulf(v[5], w5); v[6] = cmulf(v[6], w6);
    v[7] = cmulf(v[7], w7);
}

// 8x8 transpose across 8 lanes (lane index a = t&7), 8 float2 regs.
__device__ __forceinline__ void transpose8(float2* v, int a)
{
    #pragma unroll
    for (int k = 1; k < 8; k <<= 1) {
        bool up = (a & k) != 0;
        #pragma unroll
        for (int j0 = 0; j0 < 8; j0++) {
            if ((j0 & k) == 0) {
                int j1 = j0 | k;
                float sx = up ? v[j0].x : v[j1].x;
                float sy = up ? v[j0].y : v[j1].y;
                sx = __shfl_xor_sync(0xffffffffu, sx, k);
                sy = __shfl_xor_sync(0xffffffffu, sy, k);
                if (up) { v[j0].x = sx; v[j0].y = sy; }
                else    { v[j1].x = sx; v[j1].y = sy; }
            }
        }
    }
}

// one radix-8 pass in shared memory, stride H, sub-transform M=8H
template<int SGN, int H>
__device__ __forceinline__ void stage_sh(float2* s, int t)
{
    const int M = 8 * H;
    int base = (t / H) * M + (t % H);
    int a    = t % H;
    float2 v[8];
    #pragma unroll
    for (int i = 0; i < 8; i++)
        v[i] = s[SWZ(base + H * i)];
    if (SGN < 0) { dft8<SGN>(v); twiddles<SGN, M>(v, a); }
    else         { twiddles<SGN, M>(v, a); dft8<SGN>(v); }
    #pragma unroll
    for (int i = 0; i < 8; i++)
        s[SWZ(base + H * i)] = v[i];
}

// 64-thread named barrier: group = t>>6, ids 1..8
__device__ __forceinline__ void bar64(int t)
{
    asm volatile("bar.sync %0, 64;" :: "r"(1 + (t >> 6)) : "memory");
}

// ---------------- main kernel: 2 real channels per block ----------------
__global__ __launch_bounds__(TPB, 2)
void s4_fftconv_kernel(const float* __restrict__ x, float* __restrict__ y)
{
    __shared__ float2 s[LSEQ];
    const int t = threadIdx.x;
    const size_t base = (size_t)blockIdx.x * 2u * LSEQ;
    const float* x1 = x + base;
    const float* x2 = x + base + LSEQ;
    float* y1 = y + base;
    float* y2 = y + base + LSEQ;

    float2 v[8];

    // ---- forward stage 0 (M=4096, H=512): global -> regs -> shared
    #pragma unroll
    for (int b = 0; b < 8; b++)
        v[b] = make_float2(x1[t + 512 * b], x2[t + 512 * b]);
    dft8<-1>(v);
    twiddles<-1, 4096>(v, t);
    #pragma unroll
    for (int j = 0; j < 8; j++)
        s[SWZ(t + 512 * j)] = v[j];
    __syncthreads();

    stage_sh<-1, 64>(s, t);   // forward stage 1 (M=512, H=64)
    bar64(t);

    // ---- merged middle: fwd H=8 + transpose + fwd H=1 + Ksp + inv H=1 +
    //      transpose + inv H=8 — one smem round trip, all intra-warp
    {
        const int g = t >> 3;
        const int a = t & 7;
        const int mbase = 64 * g + a;
        #pragma unroll
        for (int i = 0; i < 8; i++)
            v[i] = s[SWZ(mbase + 8 * i)];
        float4 kk0, kk1, kk2, kk3;
        {
            const float4* K4 = reinterpret_cast<const float4*>(g_Ksp) + 4 * t;
            kk0 = __ldg(&K4[0]); kk1 = __ldg(&K4[1]);
            kk2 = __ldg(&K4[2]); kk3 = __ldg(&K4[3]);
        }
        dft8<-1>(v);
        twiddles<-1, 64>(v, a);
        transpose8(v, a);                 // v[d] = element 8t + d
        dft8<-1>(v);                      // fwd H=1 (no twiddle)
        v[0] = cmulf(v[0], make_float2(kk0.x, kk0.y));
        v[1] = cmulf(v[1], make_float2(kk0.z, kk0.w));
        v[2] = cmulf(v[2], make_float2(kk1.x, kk1.y));
        v[3] = cmulf(v[3], make_float2(kk1.z, kk1.w));
        v[4] = cmulf(v[4], make_float2(kk2.x, kk2.y));
        v[5] = cmulf(v[5], make_float2(kk2.z, kk2.w));
        v[6] = cmulf(v[6], make_float2(kk3.x, kk3.y));
        v[7] = cmulf(v[7], make_float2(kk3.z, kk3.w));
        dft8<1>(v);                       // inverse H=1
        transpose8(v, a);
        twiddles<1, 64>(v, a);
        dft8<1>(v);                       // inverse H=8
        #pragma unroll
        for (int i = 0; i < 8; i++)
            s[SWZ(mbase + 8 * i)] = v[i];
    }
    bar64(t);

    stage_sh<1, 64>(s, t);    // inverse stage 1
    __syncthreads();

    // ---- inverse stage 0 (M=4096, H=512): shared -> regs -> global
    #pragma unroll
    for (int j = 0; j < 8; j++)
        v[j] = s[SWZ(t + 512 * j)];
    twiddles<1, 4096>(v, t);
    dft8<1>(v);
    #pragma unroll
    for (int b = 0; b < 8; b++) {
        y1[t + 512 * b] = v[b].x;
        y2[t + 512 * b] = v[b].y;
    }
}

extern "C" void kernel_launch(void* const* d_in, const int* in_sizes, int n_in,
                              void* d_out, int out_size)
{
    const float* x   = (const float*)d_in[0];
    const float* lre = (const float*)d_in[1];
    const float* lim = (const float*)d_in[2];
    const float* pre = (const float*)d_in[3];
    const float* pim = (const float*)d_in[4];
    const float* bre = (const float*)d_in[5];
    const float* bim = (const float*)d_in[6];
    const float* cre = (const float*)d_in[7];
    const float* cim = (const float*)d_in[8];
    float* y = (float*)d_out;

    compute_K_fused<<<(((LSEQ / 2 + 1) * 4) + 255) / 256, 256>>>(lre, lim, pre, pim, bre, bim, cre, cim);
    s4_fftconv_kernel<<<NPAIR, TPB>>>(x, y);
}